// round 1
// baseline (speedup 1.0000x reference)
#include <cuda_runtime.h>
#include <cstdint>

// Problem constants
#define TT 16384   // B*S tokens
#define HH 1024    // hidden
#define II 4096    // intermediate
#define EE 8       // experts
#define TOPK 2

// ---------------- scratch (device globals; no runtime allocation) ----------
__device__ int   d_counts[EE];
__device__ int   d_offsets[EE];
__device__ int   d_tok[EE * TT];
__device__ float d_wt[EE * TT];
// Compact per-(expert,token) intermediate activations: exactly 2*T rows total.
__device__ float d_hmid[(size_t)2 * TT * II];   // 536 MB, zero-init at load

// ---------------- helpers ----------------
__device__ __forceinline__ uint32_t f2tf32(float f) {
    uint32_t r;
    asm("cvt.rna.tf32.f32 %0, %1;" : "=r"(r) : "f"(f));
    return r;
}

__device__ __forceinline__ float silu_f(float v) {
    return v / (1.0f + __expf(-v));
}

#define MMA_TF32(D, A, B_)                                                       \
    asm volatile(                                                                \
        "mma.sync.aligned.m16n8k8.row.col.f32.tf32.tf32.f32 "                    \
        "{%0,%1,%2,%3}, {%4,%5,%6,%7}, {%8,%9}, {%0,%1,%2,%3};\n"                \
        : "+f"((D)[0]), "+f"((D)[1]), "+f"((D)[2]), "+f"((D)[3])                 \
        : "r"((A)[0]), "r"((A)[1]), "r"((A)[2]), "r"((A)[3]),                    \
          "r"((B_)[0]), "r"((B_)[1]))

// ---------------- kernel 0: zero per-expert counters ----------------
__global__ void init_counts_kernel() {
    if (threadIdx.x < EE) d_counts[threadIdx.x] = 0;
}

// ---------------- kernel 1: router ----------------
// logits = x @ Wg^T (fp32), top-2 over experts, renormalized weights,
// atomic-append (token, weight) into per-expert lists.
__global__ __launch_bounds__(256)
void router_kernel(const float* __restrict__ x,
                   const float* __restrict__ Wg,
                   float* __restrict__ logits_out) {
    __shared__ float sWg[EE][HH];   // 32 KB
    for (int i = threadIdx.x; i < EE * HH; i += blockDim.x)
        sWg[i / HH][i % HH] = Wg[i];
    __syncthreads();

    const int warp = threadIdx.x >> 5;
    const int lane = threadIdx.x & 31;
    const int t = blockIdx.x * 8 + warp;   // 8 tokens per block
    if (t >= TT) return;

    const float* xr = x + (size_t)t * HH;
    float acc[EE];
#pragma unroll
    for (int e = 0; e < EE; e++) acc[e] = 0.0f;

    for (int k = lane; k < HH; k += 32) {
        float xv = xr[k];
#pragma unroll
        for (int e = 0; e < EE; e++) acc[e] += xv * sWg[e][k];
    }
#pragma unroll
    for (int off = 16; off > 0; off >>= 1) {
#pragma unroll
        for (int e = 0; e < EE; e++)
            acc[e] += __shfl_xor_sync(0xFFFFFFFFu, acc[e], off);
    }

    if (lane == 0) {
        if (logits_out) {
#pragma unroll
            for (int e = 0; e < EE; e++) logits_out[(size_t)t * EE + e] = acc[e];
        }
        // top-2 (ties -> lowest index, matching jax.lax.top_k)
        int i0 = 0; float v0 = acc[0];
#pragma unroll
        for (int e = 1; e < EE; e++) if (acc[e] > v0) { v0 = acc[e]; i0 = e; }
        int i1 = -1; float v1 = -3.4e38f;
#pragma unroll
        for (int e = 0; e < EE; e++)
            if (e != i0 && acc[e] > v1) { v1 = acc[e]; i1 = e; }
        // softmax denominator cancels in the top-k renormalization:
        // w0 = 1/(1+exp(v1-v0)), w1 = 1-w0
        float r  = expf(v1 - v0);
        float w0 = 1.0f / (1.0f + r);
        float w1 = 1.0f - w0;

        int p0 = atomicAdd(&d_counts[i0], 1);
        d_tok[i0 * TT + p0] = t;  d_wt[i0 * TT + p0] = w0;
        int p1 = atomicAdd(&d_counts[i1], 1);
        d_tok[i1 * TT + p1] = t;  d_wt[i1 * TT + p1] = w1;
    }
}

// ---------------- kernel 2: prefix scan over 8 counts ----------------
__global__ void scan_kernel() {
    int off = 0;
#pragma unroll
    for (int e = 0; e < EE; e++) { d_offsets[e] = off; off += d_counts[e]; }
}

// ---------------- kernels 3/4: tiled tf32 mma GEMM ----------------
// FIRST  : hmid[r] = silu(x[tok(r)] @ W1e^T + b1e)        (K = H = 1024)
// !FIRST : out[tok(r)] += w(r) * (hmid[r] @ W2e^T + b2e)  (K = I = 4096)
constexpr int BM = 128, BN = 128, BK = 16, BKP = 20;

template <bool FIRST>
__global__ __launch_bounds__(256)
void moe_gemm_kernel(const float* __restrict__ X,
                     const float* __restrict__ W,
                     const float* __restrict__ bias,
                     float* __restrict__ out) {
    const int e   = blockIdx.z;
    const int cnt = d_counts[e];
    const int m0  = blockIdx.y * BM;
    if (m0 >= cnt) return;
    const int n0   = blockIdx.x * BN;
    const int KDIM = FIRST ? HH : II;
    const int NDIM = FIRST ? II : HH;
    const int offs = d_offsets[e];

    __shared__ uint32_t As[BM][BKP];
    __shared__ uint32_t Bs[BN][BKP];

    const int tid = threadIdx.x;

    // loader mapping: 2 float4 chunks per thread cover 128x16 tile
    int rL[2], cL[2];
    const float* aPtr[2];
    const float* bPtr[2];
#pragma unroll
    for (int j = 0; j < 2; j++) {
        int idx = tid + j * 256;
        int row = idx >> 2;
        int col = (idx & 3) * 4;
        rL[j] = row; cL[j] = col;
        int gm = m0 + row;
        if (gm >= cnt) gm = cnt - 1;   // pad rows replicate last valid row
        if (FIRST) {
            int tok = d_tok[e * TT + gm];
            aPtr[j] = X + (size_t)tok * HH + col;
        } else {
            aPtr[j] = d_hmid + (size_t)(offs + gm) * II + col;
        }
        bPtr[j] = W + (size_t)e * ((size_t)II * HH) + (size_t)(n0 + row) * KDIM + col;
    }

    float4 va[2], vb[2];
#pragma unroll
    for (int j = 0; j < 2; j++) {
        va[j] = *(const float4*)(aPtr[j]);
        vb[j] = *(const float4*)(bPtr[j]);
    }

    const int wid = tid >> 5, lane = tid & 31;
    const int wm = (wid & 1) * 64;
    const int wn = (wid >> 1) * 32;
    const int g = lane >> 2, tg = lane & 3;

    float acc[4][4][4];
#pragma unroll
    for (int a = 0; a < 4; a++)
#pragma unroll
        for (int b = 0; b < 4; b++)
#pragma unroll
            for (int c = 0; c < 4; c++) acc[a][b][c] = 0.0f;

    for (int k0 = 0; k0 < KDIM; k0 += BK) {
#pragma unroll
        for (int j = 0; j < 2; j++) {
            uint32_t* dA = &As[rL[j]][cL[j]];
            dA[0] = f2tf32(va[j].x); dA[1] = f2tf32(va[j].y);
            dA[2] = f2tf32(va[j].z); dA[3] = f2tf32(va[j].w);
            uint32_t* dB = &Bs[rL[j]][cL[j]];
            dB[0] = f2tf32(vb[j].x); dB[1] = f2tf32(vb[j].y);
            dB[2] = f2tf32(vb[j].z); dB[3] = f2tf32(vb[j].w);
        }
        __syncthreads();

        if (k0 + BK < KDIM) {   // register prefetch of next tile
#pragma unroll
            for (int j = 0; j < 2; j++) {
                va[j] = *(const float4*)(aPtr[j] + k0 + BK);
                vb[j] = *(const float4*)(bPtr[j] + k0 + BK);
            }
        }

#pragma unroll
        for (int kk = 0; kk < BK; kk += 8) {
            uint32_t af[4][4], bf[4][2];
#pragma unroll
            for (int mf = 0; mf < 4; mf++) {
                int m = wm + mf * 16 + g;
                af[mf][0] = As[m][kk + tg];
                af[mf][1] = As[m + 8][kk + tg];
                af[mf][2] = As[m][kk + tg + 4];
                af[mf][3] = As[m + 8][kk + tg + 4];
            }
#pragma unroll
            for (int nf = 0; nf < 4; nf++) {
                int n = wn + nf * 8 + g;
                bf[nf][0] = Bs[n][kk + tg];
                bf[nf][1] = Bs[n][kk + tg + 4];
            }
#pragma unroll
            for (int mf = 0; mf < 4; mf++)
#pragma unroll
                for (int nf = 0; nf < 4; nf++)
                    MMA_TF32(acc[mf][nf], af[mf], bf[nf]);
        }
        __syncthreads();
    }

    // epilogue
#pragma unroll
    for (int mf = 0; mf < 4; mf++) {
#pragma unroll
        for (int half = 0; half < 2; half++) {
            int m = m0 + wm + mf * 16 + g + half * 8;
            if (m >= cnt) continue;
            if (FIRST) {
                float* dst = d_hmid + (size_t)(offs + m) * II + n0;
#pragma unroll
                for (int nf = 0; nf < 4; nf++) {
                    int col = wn + nf * 8 + tg * 2;
                    float bb0 = bias[(size_t)e * NDIM + n0 + col];
                    float bb1 = bias[(size_t)e * NDIM + n0 + col + 1];
                    float s0 = silu_f(acc[mf][nf][half * 2 + 0] + bb0);
                    float s1 = silu_f(acc[mf][nf][half * 2 + 1] + bb1);
                    *(float2*)(dst + col) = make_float2(s0, s1);
                }
            } else {
                int tok = d_tok[e * TT + m];
                float w = d_wt[e * TT + m];
                float* dst = out + (size_t)tok * HH + n0;
#pragma unroll
                for (int nf = 0; nf < 4; nf++) {
                    int col = wn + nf * 8 + tg * 2;
                    float bb0 = bias[(size_t)e * NDIM + n0 + col];
                    float bb1 = bias[(size_t)e * NDIM + n0 + col + 1];
                    atomicAdd(dst + col,     w * (acc[mf][nf][half * 2 + 0] + bb0));
                    atomicAdd(dst + col + 1, w * (acc[mf][nf][half * 2 + 1] + bb1));
                }
            }
        }
    }
}

// ---------------- launch ----------------
extern "C" void kernel_launch(void* const* d_in, const int* in_sizes, int n_in,
                              void* d_out, int out_size) {
    const float* x  = (const float*)d_in[0];   // [T,H]
    const float* Wg = (const float*)d_in[1];   // [E,H]
    const float* W1 = (const float*)d_in[2];   // [E,I,H]
    const float* b1 = (const float*)d_in[3];   // [E,I]
    const float* W2 = (const float*)d_in[4];   // [E,H,I]
    const float* b2 = (const float*)d_in[5];   // [E,H]
    float* out = (float*)d_out;

    // Output tuple layout: out [T,H] first, logits [T,E] appended (if present).
    float* logits = nullptr;
    if ((size_t)out_size >= (size_t)TT * HH + (size_t)TT * EE)
        logits = out + (size_t)TT * HH;

    init_counts_kernel<<<1, 32>>>();
    router_kernel<<<TT / 8, 256>>>(x, Wg, logits);
    scan_kernel<<<1, 1>>>();
    cudaMemsetAsync(out, 0, (size_t)TT * HH * sizeof(float), 0);

    dim3 g1(II / BN, TT / BM, EE);   // (32, 128, 8), most M-tiles early-exit
    moe_gemm_kernel<true><<<g1, 256>>>(x, W1, b1, nullptr);

    dim3 g2(HH / BN, TT / BM, EE);   // (8, 128, 8)
    moe_gemm_kernel<false><<<g2, 256>>>(nullptr, W2, b2, out);
}